// round 15
// baseline (speedup 1.0000x reference)
#include <cuda_runtime.h>
#include <cstdint>

// out = y where 0 < y <= 1 else 0, y = x * w[col] + b[col]
// x: [8192, 4096] f32, w/b: [4096] f32. HBM-bound elementwise.
// R15: last untried traffic path — TMA bulk (cp.async.bulk 1D) for both the
//      row load (GMEM->SMEM, mbarrier complete_tx) and the row store
//      (SMEM->GMEM, bulk_group). One 16KB row per block; compute runs
//      smem->smem with JIT __ldg w/b. B300 docs say LTS cap is
//      path-independent (TMA == LDG.cv), so predicted NEUTRAL; this closes
//      the final axis.

#define D_DIM 4096
#define ROW_BYTES (D_DIM * 4)      // 16384
#define THREADS 256
#define VEC_PER_THREAD (D_DIM / 4 / THREADS)   // 4 float4 per thread

__global__ void __launch_bounds__(THREADS)
gegate_kernel(const float* __restrict__ x,
              const float4* __restrict__ w,
              const float4* __restrict__ b,
              float* __restrict__ out)
{
    __shared__ alignas(128) float s_in[D_DIM];
    __shared__ alignas(128) float s_out[D_DIM];
    __shared__ alignas(8) uint64_t mbar;

    const int t = threadIdx.x;
    const int row = blockIdx.x;
    const float* src = x + (size_t)row * D_DIM;
    float* dst = out + (size_t)row * D_DIM;

    uint32_t mbar_addr, sin_addr, sout_addr;
    asm("{ .reg .u64 a; cvta.to.shared.u64 a, %1; cvt.u32.u64 %0, a; }"
        : "=r"(mbar_addr) : "l"(&mbar));
    asm("{ .reg .u64 a; cvta.to.shared.u64 a, %1; cvt.u32.u64 %0, a; }"
        : "=r"(sin_addr) : "l"(s_in));
    asm("{ .reg .u64 a; cvta.to.shared.u64 a, %1; cvt.u32.u64 %0, a; }"
        : "=r"(sout_addr) : "l"(s_out));

    // Init mbarrier + kick off bulk load of the whole row (single thread).
    if (t == 0) {
        asm volatile("mbarrier.init.shared.b64 [%0], 1;" :: "r"(mbar_addr) : "memory");
        asm volatile("fence.proxy.async.shared::cta;" ::: "memory");
        asm volatile("mbarrier.arrive.expect_tx.shared.b64 _, [%0], %1;"
                     :: "r"(mbar_addr), "r"((uint32_t)ROW_BYTES) : "memory");
        asm volatile(
            "cp.async.bulk.shared::cta.global.mbarrier::complete_tx::bytes "
            "[%0], [%1], %2, [%3];"
            :: "r"(sin_addr), "l"(src), "r"((uint32_t)ROW_BYTES), "r"(mbar_addr)
            : "memory");
    }
    __syncthreads();   // mbarrier visible to all before waiting

    // All threads wait for TMA completion (phase 0).
    {
        uint32_t done;
        asm volatile(
            "{\n\t.reg .pred p;\n\t"
            "mbarrier.try_wait.parity.shared.b64 p, [%1], 0;\n\t"
            "selp.b32 %0, 1, 0, p;\n\t}"
            : "=r"(done) : "r"(mbar_addr) : "memory");
        while (!done) {
            asm volatile(
                "{\n\t.reg .pred p;\n\t"
                "mbarrier.try_wait.parity.shared.b64 p, [%1], 0;\n\t"
                "selp.b32 %0, 1, 0, p;\n\t}"
                : "=r"(done) : "r"(mbar_addr) : "memory");
        }
    }

    // Compute smem -> smem. Columns are compile-time offsets t + i*THREADS.
    const float4* s_in4 = reinterpret_cast<const float4*>(s_in);
    float4* s_out4 = reinterpret_cast<float4*>(s_out);
    #pragma unroll
    for (int i = 0; i < VEC_PER_THREAD; i++) {
        const int col = t + i * THREADS;
        float4 xv = s_in4[col];
        float4 wv = __ldg(&w[col]);
        float4 bv = __ldg(&b[col]);
        float4 y;
        y.x = fmaf(xv.x, wv.x, bv.x);
        y.y = fmaf(xv.y, wv.y, bv.y);
        y.z = fmaf(xv.z, wv.z, bv.z);
        y.w = fmaf(xv.w, wv.w, bv.w);
        y.x = (y.x > 0.0f && y.x <= 1.0f) ? y.x : 0.0f;
        y.y = (y.y > 0.0f && y.y <= 1.0f) ? y.y : 0.0f;
        y.z = (y.z > 0.0f && y.z <= 1.0f) ? y.z : 0.0f;
        y.w = (y.w > 0.0f && y.w <= 1.0f) ? y.w : 0.0f;
        s_out4[col] = y;
    }
    __syncthreads();

    // Bulk store SMEM -> GMEM via TMA write path (single thread).
    if (t == 0) {
        asm volatile("fence.proxy.async.shared::cta;" ::: "memory");
        asm volatile(
            "cp.async.bulk.global.shared::cta.bulk_group [%0], [%1], %2;"
            :: "l"(dst), "r"(sout_addr), "r"((uint32_t)ROW_BYTES) : "memory");
        asm volatile("cp.async.bulk.commit_group;" ::: "memory");
        asm volatile("cp.async.bulk.wait_group 0;" ::: "memory");
    }
}

extern "C" void kernel_launch(void* const* d_in, const int* in_sizes, int n_in,
                              void* d_out, int out_size)
{
    const float* x = (const float*)d_in[0];
    const float4* w = (const float4*)d_in[1];
    const float4* b = (const float4*)d_in[2];
    float* out = (float*)d_out;

    int rows = out_size / D_DIM;          // 8192
    gegate_kernel<<<rows, THREADS>>>(x, w, b, out);
}

// round 16
// speedup vs baseline: 1.2266x; 1.2266x over previous
#include <cuda_runtime.h>

// out = y where 0 < y <= 1 else 0, y = x * w[col] + b[col]
// x: [8192, 4096] f32, w/b: [4096] f32. HBM-bound elementwise.
//
// FINAL (== R2; best measured: kernel 37.9us, bench 44.70us; reproduced 5x
// within +-0.4us bench noise). Flat grid 8192x256, 4 float4/thread,
// front-batched __ldcs x reads (MLP_p1=4), JIT __ldg w/b broadcast loads,
// __stcs streaming stores.
//
// Session evidence (R1-R15): MLP {1,4,8}, occupancy 41-82%, v4/v8 load
// widths, smem staging, persistent grid, .cs/.wb store policy, block
// {128,256,512}, load-batching order, and the TMA bulk path (single-buffered
// cp.async.bulk: -23%) — all neutral or worse. Kernel is pinned at the mixed
// read+write DRAM ceiling: 268.4 MB / 38us = 7.07 TB/s wall-clock (~88% of
// the 8 TB/s HBM spec), consistent with the path-independent LTS cap.
// Roofline reached; traffic is minimal (1 read + 1 write stream).

#define D_VEC 1024            // 4096 / 4, power of two
#define ITEMS 4               // float4s per thread
#define THREADS 256
#define CHUNK (THREADS * ITEMS)   // 1024 float4 per block == one D row

__device__ __forceinline__ float4 gate4(float4 xv, float4 wv, float4 bv)
{
    float4 y;
    y.x = fmaf(xv.x, wv.x, bv.x);
    y.y = fmaf(xv.y, wv.y, bv.y);
    y.z = fmaf(xv.z, wv.z, bv.z);
    y.w = fmaf(xv.w, wv.w, bv.w);
    y.x = (y.x > 0.0f && y.x <= 1.0f) ? y.x : 0.0f;
    y.y = (y.y > 0.0f && y.y <= 1.0f) ? y.y : 0.0f;
    y.z = (y.z > 0.0f && y.z <= 1.0f) ? y.z : 0.0f;
    y.w = (y.w > 0.0f && y.w <= 1.0f) ? y.w : 0.0f;
    return y;
}

__global__ void __launch_bounds__(THREADS)
gegate_kernel(const float4* __restrict__ x,
              const float4* __restrict__ w,
              const float4* __restrict__ b,
              float4* __restrict__ out)
{
    // Each block covers CHUNK consecutive float4s; thread t handles
    // base + i*THREADS (fully coalesced, 4 independent DRAM loads in flight).
    int base = blockIdx.x * CHUNK + threadIdx.x;

    float4 xv[ITEMS];
    #pragma unroll
    for (int i = 0; i < ITEMS; i++)
        xv[i] = __ldcs(&x[base + i * THREADS]);   // streaming: no L2 reuse

    #pragma unroll
    for (int i = 0; i < ITEMS; i++) {
        int idx = base + i * THREADS;
        int col = idx & (D_VEC - 1);
        float4 wv = __ldg(&w[col]);
        float4 bv = __ldg(&b[col]);
        __stcs(&out[idx], gate4(xv[i], wv, bv));
    }
}

extern "C" void kernel_launch(void* const* d_in, const int* in_sizes, int n_in,
                              void* d_out, int out_size)
{
    const float4* x = (const float4*)d_in[0];
    const float4* w = (const float4*)d_in[1];
    const float4* b = (const float4*)d_in[2];
    float4* out = (float4*)d_out;

    int n_vec = out_size / 4;                     // 8388608
    int blocks = n_vec / CHUNK;                   // 8192 exactly

    gegate_kernel<<<blocks, THREADS>>>(x, w, b, out);
}